// round 12
// baseline (speedup 1.0000x reference)
#include <cuda_runtime.h>
#include <cuda_bf16.h>
#include <cuda_fp16.h>
#include <math.h>

// Problem constants: B=4, L=5000, D=128, H=8, d=16, K=32
#define LQ    5000
#define MROWS 20000          // B*L  (divisible by 32)
#define DDIM  128
#define KSEL  32
#define WELEM (DDIM*DDIM)    // 16384
#define NTILES (MROWS/32)    // 625 tiles of 32 rows

// Scratch (allocation-free rule: __device__ globals)
__device__ float  g_q[MROWS * DDIM];
__device__ __half g_kh[MROWS * DDIM];
__device__ __half g_vh[MROWS * DDIM];
__device__ float  g_attn[MROWS * DDIM];
__device__ __nv_bfloat16 g_whi[4 * WELEM];
__device__ __nv_bfloat16 g_wlo[4 * WELEM];

// ---------------------------------------------------------------------------
__device__ __forceinline__ void bf16_split(float v, __nv_bfloat16& hi, __nv_bfloat16& lo)
{
    hi = __float2bfloat16(v);
    lo = __float2bfloat16(v - __bfloat162float(hi));
}

// W conversion: 4 x 16384 elements (tiny, ~2 us)
__global__ __launch_bounds__(256) void convert_w(const float* __restrict__ wq,
                                                 const float* __restrict__ wk,
                                                 const float* __restrict__ wv,
                                                 const float* __restrict__ wo)
{
    int i = blockIdx.x * blockDim.x + threadIdx.x;
    if (i >= 4 * WELEM) return;
    const float* src[4] = { wq, wk, wv, wo };
    float v = src[i >> 14][i & (WELEM - 1)];
    __nv_bfloat16 hi, lo;
    bf16_split(v, hi, lo);
    g_whi[i] = hi;
    g_wlo[i] = lo;
}

// ---------------------------------------------------------------------------
// Persistent-W 3xBF16 tensor GEMM (R8 configuration — best measured):
// C[m][n] = sum_k A[m][k]*W[n][k] (+bias). W (hi+lo bf16) resident in smem;
// block grid-strides over 32-row A tiles, A double-buffered register-staged
// and split in-kernel. 256 thr / 8 warps, warp grid 2m x 4n (tile m16xn32).
// Row stride 136 elem (272 B): ldmatrix 8-row phases conflict-free.
// ---------------------------------------------------------------------------
#define MMA_BF16(d, a, b)                                                   \
    asm volatile(                                                           \
        "mma.sync.aligned.m16n8k16.row.col.f32.bf16.bf16.f32 "              \
        "{%0,%1,%2,%3}, {%4,%5,%6,%7}, {%8,%9}, {%0,%1,%2,%3};"             \
        : "+f"(d[0]), "+f"(d[1]), "+f"(d[2]), "+f"(d[3])                    \
        : "r"(a[0]), "r"(a[1]), "r"(a[2]), "r"(a[3]), "r"(b[0]), "r"(b[1]))

__device__ __forceinline__ void ldsm4(unsigned* r, unsigned addr)
{
    asm volatile("ldmatrix.sync.aligned.m8n8.x4.shared.b16 {%0,%1,%2,%3}, [%4];"
                 : "=r"(r[0]), "=r"(r[1]), "=r"(r[2]), "=r"(r[3]) : "r"(addr));
}

#define SROWW   136                        // row stride in bf16 elems (272 B)
#define WPLANE  (128 * SROWW)              // 17408 elems
#define ATILE   (32 * SROWW)               // 4352 elems per A plane
#define OFF_WL  WPLANE
#define OFF_A   (2 * WPLANE)               // A buffers start (hi,lo per buf)
#define ABUF    (2 * ATILE)                // one A buffer (hi+lo)
#define GSMEM_ELEM (2 * WPLANE + 2 * ABUF) // 52224 elems
#define GSMEM_BYTES (GSMEM_ELEM * 2)       // 104448 B

__global__ __launch_bounds__(256, 2) void gemm_bf16(const float* __restrict__ A,
                                                    const __nv_bfloat16* __restrict__ WhiB,
                                                    const __nv_bfloat16* __restrict__ WloB,
                                                    const float* __restrict__ bias,
                                                    float* __restrict__ Cf,
                                                    __half* __restrict__ Ck,
                                                    __half* __restrict__ Cv,
                                                    int wsel)
{
    extern __shared__ __nv_bfloat16 smem[];

    const int y    = blockIdx.y;
    const int widx = wsel + y;
    const __nv_bfloat16* Wh = WhiB + widx * WELEM;
    const __nv_bfloat16* Wl = WloB + widx * WELEM;

    const int tid  = threadIdx.x;
    const int w    = tid >> 5;
    const int lane = tid & 31;
    const int wm   = (w >> 2) * 16;     // 2 warps in m
    const int wn   = (w & 3) * 32;      // 4 warps in n
    const int fr   = lane >> 2;
    const int fc   = (lane & 3) * 2;

    // ---- load W (hi+lo bf16) into smem, once ----
    #pragma unroll
    for (int it = 0; it < 8; it++) {
        int i   = tid + it * 256;            // 0..2047 (uint4 granules)
        int row = i >> 4;
        int seg = i & 15;
        *(uint4*)&smem[row * SROWW + seg * 8] =
            *(const uint4*)&Wh[row * DDIM + seg * 8];
        *(uint4*)&smem[OFF_WL + row * SROWW + seg * 8] =
            *(const uint4*)&Wl[row * DDIM + seg * 8];
    }

    const unsigned sbase = (unsigned)__cvta_generic_to_shared(&smem[0]);
    const unsigned laneA = (unsigned)((wm + (lane & 15)) * (SROWW * 2)
                                      + ((lane >> 4) & 1) * 16);
    const unsigned laneB = (unsigned)((wn + ((lane >> 4) & 1) * 8 + (lane & 7)) * (SROWW * 2)
                                      + ((lane >> 3) & 1) * 16);
    const unsigned aoff[2] = { (unsigned)(OFF_A * 2), (unsigned)((OFF_A + ABUF) * 2) };

    // A staging: thread owns row ar (8 thr/row), 16 floats at seg as*16
    const int ar = tid >> 3;            // 0..31
    const int as = tid & 7;

    float4 aR[4];
    auto stage = [&](int mt) {
        const float4* s = (const float4*)&A[(size_t)(mt * 32 + ar) * DDIM + as * 16];
        aR[0] = s[0]; aR[1] = s[1]; aR[2] = s[2]; aR[3] = s[3];
    };
    auto commit = [&](int b) {
        __nv_bfloat16* ah = &smem[OFF_A + b * ABUF];
        __nv_bfloat16* al = ah + ATILE;
        union { __nv_bfloat16 h[16]; uint4 u[2]; } H, L;
        const float* af = (const float*)aR;
        #pragma unroll
        for (int i = 0; i < 16; i++) bf16_split(af[i], H.h[i], L.h[i]);
        uint4* dh = (uint4*)&ah[ar * SROWW + as * 16];
        uint4* dl = (uint4*)&al[ar * SROWW + as * 16];
        dh[0] = H.u[0]; dh[1] = H.u[1];
        dl[0] = L.u[0]; dl[1] = L.u[1];
    };

    int mt = blockIdx.x;
    int buf = 0;
    if (mt < NTILES) { stage(mt); commit(0); }
    __syncthreads();                     // covers W load + first A commit

    while (mt < NTILES) {
        const int nxt = mt + gridDim.x;
        if (nxt < NTILES) stage(nxt);

        float acc[4][4] = {};
        const unsigned ab = sbase + aoff[buf];

        #pragma unroll
        for (int ks = 0; ks < 8; ks++) {
            unsigned ah[4], al[4];
            ldsm4(ah, ab + laneA + (unsigned)(ks * 32));
            ldsm4(al, ab + (unsigned)(ATILE * 2) + laneA + (unsigned)(ks * 32));
            #pragma unroll
            for (int ntp = 0; ntp < 2; ntp++) {
                unsigned bh[4], bl[4];
                const unsigned bo = laneB + (unsigned)(ntp * 16 * SROWW * 2 + ks * 32);
                ldsm4(bh, sbase + bo);
                ldsm4(bl, sbase + (unsigned)(OFF_WL * 2) + bo);
                MMA_BF16(acc[ntp * 2],     ah, (bh + 0));
                MMA_BF16(acc[ntp * 2],     ah, (bl + 0));
                MMA_BF16(acc[ntp * 2],     al, (bh + 0));
                MMA_BF16(acc[ntp * 2 + 1], ah, (bh + 2));
                MMA_BF16(acc[ntp * 2 + 1], ah, (bl + 2));
                MMA_BF16(acc[ntp * 2 + 1], al, (bh + 2));
            }
        }

        const int mrow = mt * 32 + wm + fr;
        if (y == 0) {
            #pragma unroll
            for (int nt = 0; nt < 4; nt++) {
                const int n = wn + nt * 8 + fc;
                float2 bb = make_float2(0.f, 0.f);
                if (bias) bb = *(const float2*)&bias[n];
                *(float2*)&Cf[(size_t)mrow * DDIM + n] =
                    make_float2(acc[nt][0] + bb.x, acc[nt][1] + bb.y);
                *(float2*)&Cf[(size_t)(mrow + 8) * DDIM + n] =
                    make_float2(acc[nt][2] + bb.x, acc[nt][3] + bb.y);
            }
        } else {
            __half* H = (y == 1) ? Ck : Cv;
            #pragma unroll
            for (int nt = 0; nt < 4; nt++) {
                const int n = wn + nt * 8 + fc;
                *(__half2*)&H[(size_t)mrow * DDIM + n] =
                    __floats2half2_rn(acc[nt][0], acc[nt][1]);
                *(__half2*)&H[(size_t)(mrow + 8) * DDIM + n] =
                    __floats2half2_rn(acc[nt][2], acc[nt][3]);
            }
        }

        if (nxt < NTILES) commit(buf ^ 1);
        __syncthreads();
        buf ^= 1;
        mt = nxt;
    }
}

// ---------------------------------------------------------------------------
// Attention (R10 — best measured): 128 thr / 1 query, V prefetch before
// softmax, no-max softmax (scores ~N(0,1)); fp16 K/V, fp32 Q/math.
// ---------------------------------------------------------------------------
__global__ __launch_bounds__(128) void attn_kernel(const int* __restrict__ kidx)
{
    __shared__ int   sIdx[KSEL];
    __shared__ float sS[8][33];
    __shared__ float sAcc[4][DDIM];

    const int bl   = blockIdx.x;
    const int l    = bl % LQ;
    const int base = bl - l;
    const int t    = threadIdx.x;
    const int w    = t >> 5;
    const int lane = t & 31;
    const int h    = lane >> 2;

    if (t < KSEL) sIdx[t] = kidx[l * KSEL + t];

    const float4 q4 = *(const float4*)&g_q[(size_t)bl * DDIM + lane * 4];
    __syncthreads();

    int rows[8];
    #pragma unroll
    for (int i = 0; i < 8; i++) rows[i] = base + sIdx[i * 4 + w];

    // score pass
    #pragma unroll
    for (int i = 0; i < 8; i++) {
        const uint2 kv = *(const uint2*)&g_kh[(size_t)rows[i] * DDIM + lane * 4];
        const float2 f0 = __half22float2(*(const __half2*)&kv.x);
        const float2 f1 = __half22float2(*(const __half2*)&kv.y);
        float p = f0.x * q4.x + f0.y * q4.y + f1.x * q4.z + f1.y * q4.w;
        p += __shfl_xor_sync(0xffffffffu, p, 1);
        p += __shfl_xor_sync(0xffffffffu, p, 2);
        if ((lane & 3) == 0) sS[h][i * 4 + w] = p * 0.25f;
    }

    // V prefetch (independent of softmax -> latency hidden)
    uint2 vv[8];
    #pragma unroll
    for (int i = 0; i < 8; i++)
        vv[i] = *(const uint2*)&g_vh[(size_t)rows[i] * DDIM + lane * 4];

    __syncthreads();

    // softmax (no max subtraction): warp w -> heads 2w, 2w+1
    #pragma unroll
    for (int j = 0; j < 2; j++) {
        const int hh = w * 2 + j;
        const float e = __expf(sS[hh][lane]);
        float sum = e;
        #pragma unroll
        for (int ofs = 16; ofs; ofs >>= 1)
            sum += __shfl_xor_sync(0xffffffffu, sum, ofs);
        sS[hh][lane] = e * __frcp_rn(sum);
    }
    __syncthreads();

    // weighted V sum from registers
    float4 acc = make_float4(0.f, 0.f, 0.f, 0.f);
    #pragma unroll
    for (int i = 0; i < 8; i++) {
        const float2 f0 = __half22float2(*(const __half2*)&vv[i].x);
        const float2 f1 = __half22float2(*(const __half2*)&vv[i].y);
        const float a = sS[h][i * 4 + w];
        acc.x += a * f0.x;
        acc.y += a * f0.y;
        acc.z += a * f1.x;
        acc.w += a * f1.y;
    }
    *(float4*)&sAcc[w][lane * 4] = acc;
    __syncthreads();

    g_attn[(size_t)bl * DDIM + t] = sAcc[0][t] + sAcc[1][t] + sAcc[2][t] + sAcc[3][t];
}

// ---------------------------------------------------------------------------
extern "C" void kernel_launch(void* const* d_in, const int* in_sizes, int n_in,
                              void* d_out, int out_size)
{
    const float* x    = (const float*)d_in[0];
    const int*   kidx = (const int*)d_in[1];
    const float* Wq   = (const float*)d_in[2];
    const float* Wk   = (const float*)d_in[3];
    const float* Wv   = (const float*)d_in[4];
    const float* Wo   = (const float*)d_in[5];
    const float* bo   = (const float*)d_in[6];
    float* out = (float*)d_out;

    float *q, *attn;
    __half *kh, *vh;
    __nv_bfloat16 *whi, *wlo;
    cudaGetSymbolAddress((void**)&q,    g_q);
    cudaGetSymbolAddress((void**)&kh,   g_kh);
    cudaGetSymbolAddress((void**)&vh,   g_vh);
    cudaGetSymbolAddress((void**)&attn, g_attn);
    cudaGetSymbolAddress((void**)&whi,  g_whi);
    cudaGetSymbolAddress((void**)&wlo,  g_wlo);

    // Raise dynamic smem cap (idempotent; not a stream op; every call).
    cudaFuncSetAttribute(gemm_bf16,
                         cudaFuncAttributeMaxDynamicSharedMemorySize,
                         GSMEM_BYTES);

    convert_w<<<(4 * WELEM + 255) / 256, 256>>>(Wq, Wk, Wv, Wo);

    // QKV: 96 x 3 persistent blocks (~2/SM), ~6.5 tiles each.
    gemm_bf16<<<dim3(96, 3), 256, GSMEM_BYTES>>>(x, whi, wlo, nullptr,
                                                 q, kh, vh, 0);

    attn_kernel<<<MROWS, 128>>>(kidx);

    // Wo: 296 persistent blocks (2/SM), ~2.1 tiles each, bias, fp32 out.
    gemm_bf16<<<dim3(296, 1), 256, GSMEM_BYTES>>>(attn, whi, wlo, bo,
                                                  out, nullptr, nullptr, 3);
}